// round 10
// baseline (speedup 1.0000x reference)
#include <cuda_runtime.h>
#include <cuda_bf16.h>
#include <math.h>
#include <stdint.h>

// Problem constants
#define Bv    32
#define Nv    4096
#define INPv  512
#define Sv    8
#define Dv    256
#define Hv    512
#define ROWSv (Bv*Nv)   // 131072
#define SRv   (Bv*Sv)   // 256

// ---------------- scratch (static device globals; no allocs allowed) ----------------
// g_k/g_v hold bf16 now (aliased): 131072 rows x 256 bf16 = 64 MB each
__device__ __align__(16) float g_k[33554432];
__device__ __align__(16) float g_v[33554432];
__device__ __align__(16) float g_stats[262144];    // [ROWS][2] mean,rstd
__device__ __align__(16) float g_wsum[512];        // colsum of [Wk|Wv]
__device__ __align__(16) float g_wt[262144];       // transposed fused W: [512 n][512 k]
__device__ __align__(16) float g_slots[65536];     // [256][256]
__device__ __align__(16) float g_sln[65536];
__device__ __align__(16) float g_q[65536];
__device__ __align__(16) float g_upd[65536];
__device__ __align__(16) float g_colsum[256];
__device__ __align__(16) float g_gx[196608];       // [256][768]
__device__ __align__(16) float g_gh[196608];
__device__ __align__(16) float g_h1[131072];       // [256][512]
__device__ __align__(16) float g_y[65536];

__device__ __forceinline__ uint32_t smem_u32(const void* p) {
    uint32_t a;
    asm("{ .reg .u64 t; cvta.to.shared.u64 t, %1; cvt.u32.u64 %0, t; }" : "=r"(a) : "l"(p));
    return a;
}
__device__ __forceinline__ void cpasync16(uint32_t d, const void* g) {
    asm volatile("cp.async.cg.shared.global [%0], [%1], 16;" :: "r"(d), "l"(g));
}
#define CP_COMMIT() asm volatile("cp.async.commit_group;" ::: "memory")
#define CP_WAIT0()  asm volatile("cp.async.wait_group 0;" ::: "memory")

// ---------------- LN stats: mean/rstd per input row of 512 ----------------
__global__ void ln_stats_kernel(const float* __restrict__ X) {
    int warp = threadIdx.x >> 5, lane = threadIdx.x & 31;
    int row  = blockIdx.x * 8 + warp;
    const float* xr = X + (size_t)row * INPv;
    float s = 0.f, s2 = 0.f;
#pragma unroll
    for (int j = 0; j < 4; j++) {
        float4 v4 = *(const float4*)(xr + lane * 4 + 128 * j);
        s  += v4.x + v4.y + v4.z + v4.w;
        s2 += v4.x * v4.x + v4.y * v4.y + v4.z * v4.z + v4.w * v4.w;
    }
#pragma unroll
    for (int off = 16; off; off >>= 1) {
        s  += __shfl_down_sync(0xffffffffu, s,  off);
        s2 += __shfl_down_sync(0xffffffffu, s2, off);
    }
    if (!lane) {
        float m   = s * (1.f / INPv);
        float var = s2 * (1.f / INPv) - m * m;
        g_stats[row * 2]     = m;
        g_stats[row * 2 + 1] = rsqrtf(var + 1e-5f);
    }
}

// ---------------- column sums of Wk|Wv (parallel) ----------------
__global__ void wsum_kernel(const float* __restrict__ Wk, const float* __restrict__ Wv) {
    __shared__ float red[4][64];
    int b = blockIdx.x;                 // 8 blocks x 64 cols
    int c0 = b * 64;
    int col = threadIdx.x & 63, part = threadIdx.x >> 6;
    const float* W = (c0 < 256) ? Wk : Wv;
    int cc = (c0 & 255) + col;
    float s = 0.f;
    for (int k = part * 128; k < part * 128 + 128; k++) s += W[k * 256 + cc];
    red[part][col] = s;
    __syncthreads();
    if (threadIdx.x < 64) {
        g_wsum[c0 + threadIdx.x] = red[0][threadIdx.x] + red[1][threadIdx.x]
                                 + red[2][threadIdx.x] + red[3][threadIdx.x];
    }
}

// ---------------- transpose fused weights: g_wt[n][k] = W[k][n] ----------------
__global__ void transpose_w_kernel(const float* __restrict__ Wk, const float* __restrict__ Wv) {
    __shared__ float t[32][33];
    int n0 = blockIdx.x * 32, k0 = blockIdx.y * 32;
    int tx = threadIdx.x, ty = threadIdx.y;     // (32, 8)
    const float* W = (n0 < 256) ? Wk : Wv;
    int col0 = n0 & 255;
#pragma unroll
    for (int j = 0; j < 4; j++) {
        int k = k0 + ty + 8 * j;
        t[ty + 8 * j][tx] = W[(size_t)k * 256 + col0 + tx];
    }
    __syncthreads();
#pragma unroll
    for (int j = 0; j < 4; j++) {
        int n = n0 + ty + 8 * j;
        g_wt[(size_t)n * 512 + k0 + tx] = t[tx][ty + 8 * j];
    }
}

// ---------------- tf32 mma.sync projection with cp.async pipeline ----------------
#define PITCH 36
#define ABYTES (128 * PITCH * 4)      // 18432 per buffer

__global__ __launch_bounds__(256, 2)
void proj_mma_kernel(const float* __restrict__ X) {
    extern __shared__ char dsm[];
    uint32_t sb = smem_u32(dsm);
    int n0   = blockIdx.x * 128;
    int row0 = blockIdx.y * 128;
    int tid  = threadIdx.x;
    int wid  = tid >> 5, lane = tid & 31;
    int warp_m = wid >> 2, warp_n = wid & 3;
    int mb = warp_m * 64, nb = warp_n * 32;
    int grp = lane >> 2, q = lane & 3;
    int lr = tid >> 3, lc = tid & 7;    // load row-base / float4 slot

    float acc[4][4][4];
#pragma unroll
    for (int f = 0; f < 4; f++)
#pragma unroll
        for (int g = 0; g < 4; g++)
#pragma unroll
            for (int c = 0; c < 4; c++) acc[f][g][c] = 0.f;

    auto issue = [&](int c, int buf) {
        const float* gA = X    + (size_t)(row0 + lr) * 512 + c * 32 + lc * 4;
        const float* gB = g_wt + (size_t)(n0   + lr) * 512 + c * 32 + lc * 4;
        uint32_t dA = sb + buf * ABYTES       + (lr * PITCH + lc * 4) * 4;
        uint32_t dB = sb + (2 + buf) * ABYTES + (lr * PITCH + lc * 4) * 4;
#pragma unroll
        for (int j = 0; j < 4; j++) {
            cpasync16(dA + j * 32 * PITCH * 4, gA + (size_t)j * 32 * 512);
            cpasync16(dB + j * 32 * PITCH * 4, gB + (size_t)j * 32 * 512);
        }
    };

    issue(0, 0);
    CP_COMMIT();

    int buf = 0;
    for (int c = 0; c < 16; c++) {
        CP_WAIT0();
        __syncthreads();
        if (c < 15) { issue(c + 1, buf ^ 1); CP_COMMIT(); }

        const float* As = (const float*)(dsm + buf * ABYTES);
        const float* Bs = (const float*)(dsm + (2 + buf) * ABYTES);
#pragma unroll
        for (int ks = 0; ks < 4; ks++) {
            float2 bfr[4];
#pragma unroll
            for (int g = 0; g < 4; g++)
                bfr[g] = *(const float2*)(Bs + (nb + g * 8 + grp) * PITCH + 8 * ks + 2 * q);
#pragma unroll
            for (int f = 0; f < 4; f++) {
                float2 ua = *(const float2*)(As + (mb + f * 16 + grp)     * PITCH + 8 * ks + 2 * q);
                float2 va = *(const float2*)(As + (mb + f * 16 + grp + 8) * PITCH + 8 * ks + 2 * q);
                uint32_t a0 = __float_as_uint(ua.x), a1 = __float_as_uint(va.x);
                uint32_t a2 = __float_as_uint(ua.y), a3 = __float_as_uint(va.y);
#pragma unroll
                for (int g = 0; g < 4; g++) {
                    asm volatile(
                        "mma.sync.aligned.m16n8k8.row.col.f32.tf32.tf32.f32 "
                        "{%0,%1,%2,%3}, {%4,%5,%6,%7}, {%8,%9}, {%0,%1,%2,%3};"
                        : "+f"(acc[f][g][0]), "+f"(acc[f][g][1]),
                          "+f"(acc[f][g][2]), "+f"(acc[f][g][3])
                        : "r"(a0), "r"(a1), "r"(a2), "r"(a3),
                          "r"(__float_as_uint(bfr[g].x)), "r"(__float_as_uint(bfr[g].y)));
                }
            }
        }
        buf ^= 1;
    }

    // epilogue: LN fold + store bf16 pairs
    __nv_bfloat16* kh = (__nv_bfloat16*)g_k;
    __nv_bfloat16* vh = (__nv_bfloat16*)g_v;
#pragma unroll
    for (int f = 0; f < 4; f++) {
        int r0g = row0 + mb + f * 16 + grp;
        int r1g = r0g + 8;
        float m0 = g_stats[r0g * 2],     s0 = g_stats[r0g * 2 + 1];
        float m1 = g_stats[r1g * 2],     s1 = g_stats[r1g * 2 + 1];
        float mr0 = m0 * s0, mr1 = m1 * s1;
#pragma unroll
        for (int g = 0; g < 4; g++) {
            int nglob = n0 + nb + g * 8 + q * 2;
            float ws0 = g_wsum[nglob], ws1 = g_wsum[nglob + 1];
            __nv_bfloat162 o0 = __floats2bfloat162_rn(
                s0 * acc[f][g][0] - mr0 * ws0, s0 * acc[f][g][1] - mr0 * ws1);
            __nv_bfloat162 o1 = __floats2bfloat162_rn(
                s1 * acc[f][g][2] - mr1 * ws0, s1 * acc[f][g][3] - mr1 * ws1);
            if (nglob < 256) {
                *(__nv_bfloat162*)(kh + (size_t)r0g * 256 + nglob) = o0;
                *(__nv_bfloat162*)(kh + (size_t)r1g * 256 + nglob) = o1;
            } else {
                *(__nv_bfloat162*)(vh + (size_t)r0g * 256 + nglob - 256) = o0;
                *(__nv_bfloat162*)(vh + (size_t)r1g * 256 + nglob - 256) = o1;
            }
        }
    }
}

// ---------------- slots init ----------------
__global__ void init_slots_kernel(const float* __restrict__ noise,
                                  const float* __restrict__ mu,
                                  const float* __restrict__ ls) {
    int i = blockIdx.x * 256 + threadIdx.x;   // 65536
    int d = i & 255;
    g_slots[i] = mu[d] + expf(ls[d]) * noise[i];
}

// ---------------- block LayerNorm over 256 (blockDim=256) ----------------
__device__ __forceinline__ float block_ln256(float v) {
    __shared__ float red[66];
    float s = v, s2 = v * v;
    int lane = threadIdx.x & 31, warp = threadIdx.x >> 5;
#pragma unroll
    for (int off = 16; off; off >>= 1) {
        s  += __shfl_down_sync(0xffffffffu, s,  off);
        s2 += __shfl_down_sync(0xffffffffu, s2, off);
    }
    if (!lane) { red[warp] = s; red[32 + warp] = s2; }
    __syncthreads();
    if (threadIdx.x == 0) {
        float ts = 0.f, t2 = 0.f;
#pragma unroll
        for (int i = 0; i < 8; i++) { ts += red[i]; t2 += red[32 + i]; }
        float m   = ts * (1.f / 256.f);
        float var = t2 * (1.f / 256.f) - m * m;
        red[64] = m;
        red[65] = rsqrtf(var + 1e-5f);
    }
    __syncthreads();
    return (v - red[64]) * red[65];
}

// ---------------- slots LN + q = s_ln @ Wq + zero accumulators ----------------
__global__ void slot_ln_q_kernel(const float* __restrict__ Wq) {
    __shared__ float sln[256];
    int row = blockIdx.x, t = threadIdx.x;
    float v  = g_slots[row * 256 + t];
    float nv = block_ln256(v);
    g_sln[row * 256 + t] = nv;
    sln[t] = nv;
    g_upd[row * 256 + t] = 0.f;
    if (t == 0) g_colsum[row] = 0.f;
    __syncthreads();
    float a0 = 0.f, a1 = 0.f, a2 = 0.f, a3 = 0.f;
#pragma unroll 2
    for (int k = 0; k < 256; k += 4) {
        a0 += sln[k]     * Wq[(k)     * 256 + t];
        a1 += sln[k + 1] * Wq[(k + 1) * 256 + t];
        a2 += sln[k + 2] * Wq[(k + 2) * 256 + t];
        a3 += sln[k + 3] * Wq[(k + 3) * 256 + t];
    }
    g_q[row * 256 + t] = (a0 + a1) + (a2 + a3);
}

// ---------------- fused attention + updates (bf16 k/v) ----------------
// grid (32 n-chunks, 32 batches), 256 threads.
// phase1: lane = 8*sub + di; warp handles 16 n rows in 4 quads of 4 (sub).
//   di slices d into 8 pieces; only 3 shfl levels; softmax distributed (lane di owns slot di).
// phase2: thread t owns d=t; p^T v with bf16 v.
__global__ __launch_bounds__(256)
void attn_upd_kernel() {
    __shared__ float qs[2048];       // [8][256]
    __shared__ float ps[128 * 8];
    int b  = blockIdx.y;
    int n0 = blockIdx.x * 128;
    int tid = threadIdx.x;
    int warp = tid >> 5, lane = tid & 31;
    int sub = lane >> 3, di = lane & 7;
    const __nv_bfloat16* kh = (const __nv_bfloat16*)g_k;
    const __nv_bfloat16* vh = (const __nv_bfloat16*)g_v;

    for (int i = tid; i < 2048; i += 256) qs[i] = g_q[(size_t)b * 2048 + i];
    __syncthreads();

    const float scale = 0.0625f;   // 1/sqrt(256)
    float csum_l = 0.f;            // partial colsum for slot s = di
#pragma unroll
    for (int qd = 0; qd < 4; qd++) {
        int nl = warp * 16 + qd * 4 + sub;       // local n 0..127
        const __nv_bfloat16* kp = kh + ((size_t)(b * Nv + n0 + nl)) * 256;
        float part[8] = {};
#pragma unroll
        for (int j = 0; j < 16; j++) {
            __nv_bfloat162 kk = *(const __nv_bfloat162*)(kp + j * 16 + 2 * di);
            float k0 = __bfloat162float(kk.x), k1 = __bfloat162float(kk.y);
#pragma unroll
            for (int s = 0; s < 8; s++) {
                float2 qv = *(const float2*)(qs + s * 256 + j * 16 + 2 * di);
                part[s] += k0 * qv.x + k1 * qv.y;
            }
        }
#pragma unroll
        for (int off = 1; off < 8; off <<= 1)
#pragma unroll
            for (int s = 0; s < 8; s++)
                part[s] += __shfl_xor_sync(0xffffffffu, part[s], off);
        // all 8 di-lanes of this sub hold the full 8 logits for row nl
        float m = -1e30f;
#pragma unroll
        for (int s = 0; s < 8; s++) m = fmaxf(m, part[s] * scale);
        float sum = 0.f;
        float e[8];
#pragma unroll
        for (int s = 0; s < 8; s++) { e[s] = __expf(part[s] * scale - m); sum += e[s]; }
        float p = e[di] / sum + 1e-8f;
        ps[nl * 8 + di] = p;
        csum_l += p;
    }
    atomicAdd(&g_colsum[b * 8 + di], csum_l);
    __syncthreads();

    // phase 2: p^T v
    int d = tid;
    float acc[8] = {};
    const __nv_bfloat16* vb = vh + ((size_t)(b * Nv + n0)) * 256;
#pragma unroll 4
    for (int n = 0; n < 128; n++) {
        float vv = __bfloat162float(vb[(size_t)n * 256 + d]);
#pragma unroll
        for (int s = 0; s < 8; s++) acc[s] += ps[n * 8 + s] * vv;
    }
#pragma unroll
    for (int s = 0; s < 8; s++) atomicAdd(&g_upd[(b * 8 + s) * 256 + d], acc[s]);
}

// ---------------- merged GRU gate GEMMs (gx and gh in one launch) ----------------
__global__ __launch_bounds__(256)
void gru_gemm_kernel(const float* __restrict__ wih, const float* __restrict__ whh,
                     const float* __restrict__ bih, const float* __restrict__ bhh) {
    __shared__ float As[8 * 68];
    __shared__ float Bs[8 * 68];
    int path = blockIdx.x / 12;
    int bxl  = blockIdx.x - path * 12;
    const float* A    = path ? g_sln : g_upd;
    const float* Bm   = path ? whh   : wih;
    const float* bias = path ? bhh   : bih;
    float* C          = path ? g_gh  : g_gx;
    const int N = 768, K = 256;
    int bm = blockIdx.y * 64, bn = bxl * 64;
    int tid = threadIdx.x;
    int ty = tid >> 4, tx = tid & 15;

    float inv = 1.f;
    int arow = bm + (tid >> 1);
    if (tid < 128 && path == 0) inv = 1.f / g_colsum[arow];

    float acc[4][4] = {};
    for (int k0 = 0; k0 < K; k0 += 8) {
        if (tid < 128) {
            int row = tid >> 1, part = tid & 1;
            float4 av = *(const float4*)(A + (size_t)(bm + row) * K + k0 + part * 4);
            int kk = part * 4;
            As[(kk + 0) * 68 + row] = av.x * inv;
            As[(kk + 1) * 68 + row] = av.y * inv;
            As[(kk + 2) * 68 + row] = av.z * inv;
            As[(kk + 3) * 68 + row] = av.w * inv;
        } else {
            int t2 = tid - 128;
            int n = t2 >> 1, part = t2 & 1;
            float4 bv = *(const float4*)(Bm + (size_t)(bn + n) * K + k0 + part * 4);
            int kk = part * 4;
            Bs[(kk + 0) * 68 + n] = bv.x;
            Bs[(kk + 1) * 68 + n] = bv.y;
            Bs[(kk + 2) * 68 + n] = bv.z;
            Bs[(kk + 3) * 68 + n] = bv.w;
        }
        __syncthreads();
#pragma unroll
        for (int kk = 0; kk < 8; kk++) {
            float4 a = *(const float4*)(As + kk * 68 + ty * 4);
            float4 bq = *(const float4*)(Bs + kk * 68 + tx * 4);
            float av[4] = {a.x, a.y, a.z, a.w};
            float bw[4] = {bq.x, bq.y, bq.z, bq.w};
#pragma unroll
            for (int i = 0; i < 4; i++)
#pragma unroll
                for (int j = 0; j < 4; j++)
                    acc[i][j] += av[i] * bw[j];
        }
        __syncthreads();
    }
#pragma unroll
    for (int i = 0; i < 4; i++) {
        int r = bm + ty * 4 + i;
#pragma unroll
        for (int j = 0; j < 4; j++) {
            int c = bn + tx * 4 + j;
            C[(size_t)r * N + c] = acc[i][j] + bias[c];
        }
    }
}

// ---------------- small GEMM: C[M,N] = A[M,K] @ B + bias (B k-major) ----------------
template<bool RELU, bool ACCUM>
__global__ __launch_bounds__(256)
void gemm64_kernel(const float* __restrict__ A, const float* __restrict__ Bm,
                   const float* __restrict__ bias, float* __restrict__ C,
                   int M, int N, int K, float* __restrict__ out2) {
    __shared__ float As[8 * 68];
    __shared__ float Bs[8 * 68];
    int bm = blockIdx.y * 64, bn = blockIdx.x * 64;
    int tid = threadIdx.x;
    int ty = tid >> 4, tx = tid & 15;
    float acc[4][4] = {};
    for (int k0 = 0; k0 < K; k0 += 8) {
        if (tid < 128) {
            int row = tid >> 1, part = tid & 1;
            float4 av = *(const float4*)(A + (size_t)(bm + row) * K + k0 + part * 4);
            int kk = part * 4;
            As[(kk + 0) * 68 + row] = av.x;
            As[(kk + 1) * 68 + row] = av.y;
            As[(kk + 2) * 68 + row] = av.z;
            As[(kk + 3) * 68 + row] = av.w;
        } else {
            int t2 = tid - 128;
            int kk = t2 >> 4, q = t2 & 15;
            float4 bv = *(const float4*)(Bm + (size_t)(k0 + kk) * N + bn + q * 4);
            *(float4*)(Bs + kk * 68 + q * 4) = bv;
        }
        __syncthreads();
#pragma unroll
        for (int kk = 0; kk < 8; kk++) {
            float4 a = *(const float4*)(As + kk * 68 + ty * 4);
            float4 bq = *(const float4*)(Bs + kk * 68 + tx * 4);
            float av[4] = {a.x, a.y, a.z, a.w};
            float bw[4] = {bq.x, bq.y, bq.z, bq.w};
#pragma unroll
            for (int i = 0; i < 4; i++)
#pragma unroll
                for (int j = 0; j < 4; j++)
                    acc[i][j] += av[i] * bw[j];
        }
        __syncthreads();
    }
#pragma unroll
    for (int i = 0; i < 4; i++) {
        int r = bm + ty * 4 + i;
#pragma unroll
        for (int j = 0; j < 4; j++) {
            int c = bn + tx * 4 + j;
            float v = acc[i][j] + bias[c];
            if (RELU) v = fmaxf(v, 0.f);
            if (ACCUM) {
                float nv = C[(size_t)r * N + c] + v;
                C[(size_t)r * N + c] = nv;
                if (out2) out2[(size_t)r * N + c] = nv;
            } else {
                C[(size_t)r * N + c] = v;
            }
        }
    }
}

// ---------------- GRU combine + LN(y) fused ----------------
__global__ void gru_lny_kernel() {
    int row = blockIdx.x, t = threadIdx.x;
    int i = row * 256 + t;
    const float* gx = g_gx + row * 768;
    const float* gh = g_gh + row * 768;
    float r  = 1.f / (1.f + __expf(-(gx[t] + gh[t])));
    float z  = 1.f / (1.f + __expf(-(gx[256 + t] + gh[256 + t])));
    float nn = tanhf(gx[512 + t] + r * gh[512 + t]);
    float h  = (1.f - z) * nn + z * g_sln[i];
    g_slots[i] = h;
    g_y[i] = block_ln256(h);
}

// =====================================================================
extern "C" void kernel_launch(void* const* d_in, const int* in_sizes, int n_in,
                              void* d_out, int out_size) {
    (void)in_sizes; (void)n_in; (void)out_size;
    const float* inputs = (const float*)d_in[0];
    const float* noise  = (const float*)d_in[1];
    const float* Wk     = (const float*)d_in[2];
    const float* Wv     = (const float*)d_in[3];
    const float* Wq     = (const float*)d_in[4];
    const float* mu     = (const float*)d_in[5];
    const float* ls     = (const float*)d_in[6];
    const float* wih    = (const float*)d_in[7];
    const float* whh    = (const float*)d_in[8];
    const float* bih    = (const float*)d_in[9];
    const float* bhh    = (const float*)d_in[10];
    const float* w1     = (const float*)d_in[11];
    const float* b1     = (const float*)d_in[12];
    const float* w2     = (const float*)d_in[13];
    const float* b2     = (const float*)d_in[14];

    float *p_h1, *p_y, *p_slots;
    cudaGetSymbolAddress((void**)&p_h1,    g_h1);
    cudaGetSymbolAddress((void**)&p_y,     g_y);
    cudaGetSymbolAddress((void**)&p_slots, g_slots);

    cudaFuncSetAttribute(proj_mma_kernel,
                         cudaFuncAttributeMaxDynamicSharedMemorySize, 4 * ABYTES);

    ln_stats_kernel<<<ROWSv / 8, 256>>>(inputs);
    wsum_kernel<<<8, 256>>>(Wk, Wv);
    transpose_w_kernel<<<dim3(16, 16), dim3(32, 8)>>>(Wk, Wv);
    proj_mma_kernel<<<dim3(4, 1024), 256, 4 * ABYTES>>>(inputs);
    init_slots_kernel<<<256, 256>>>(noise, mu, ls);

    for (int it = 0; it < 3; it++) {
        slot_ln_q_kernel<<<256, 256>>>(Wq);
        attn_upd_kernel<<<dim3(32, 32), 256>>>();
        gru_gemm_kernel<<<dim3(24, 4), 256>>>(wih, whh, bih, bhh);
        gru_lny_kernel<<<256, 256>>>();
        gemm64_kernel<true,  false><<<dim3(8, 4), 256>>>(p_y,  w1, b1, p_h1,    256, 512, 256, nullptr);
        gemm64_kernel<false, true ><<<dim3(4, 4), 256>>>(p_h1, w2, b2, p_slots, 256, 256, 512,
                                                         (it == 2) ? (float*)d_out : nullptr);
    }
}

// round 11
// speedup vs baseline: 1.4612x; 1.4612x over previous
#include <cuda_runtime.h>
#include <cuda_bf16.h>
#include <math.h>
#include <stdint.h>

// Problem constants
#define Bv    32
#define Nv    4096
#define INPv  512
#define Sv    8
#define Dv    256
#define Hv    512
#define ROWSv (Bv*Nv)   // 131072
#define SRv   (Bv*Sv)   // 256

// ---------------- scratch (static device globals; no allocs allowed) ----------------
// g_k/g_v hold bf16: 131072 rows x 256 bf16 = 64 MB each
__device__ __align__(16) float g_k[16777216];
__device__ __align__(16) float g_v[16777216];
__device__ __align__(16) uint16_t g_xh[67108864];  // bf16 image of X, MMA-swizzled [row][1024B]
__device__ __align__(16) uint16_t g_wth[262144];   // bf16 image of fused W^T [n][1024B]
__device__ __align__(16) float g_stats[262144];    // [ROWS][2] mean,rstd
__device__ __align__(16) float g_wsum[512];        // colsum of [Wk|Wv]
__device__ __align__(16) float g_slots[65536];     // [256][256]
__device__ __align__(16) float g_sln[65536];
__device__ __align__(16) float g_q[65536];
__device__ __align__(16) float g_upd[65536];
__device__ __align__(16) float g_colsum[256];
__device__ __align__(16) float g_gx[196608];       // [256][768]
__device__ __align__(16) float g_gh[196608];
__device__ __align__(16) float g_h1[131072];       // [256][512]
__device__ __align__(16) float g_y[65536];

__device__ __forceinline__ uint32_t smem_u32(const void* p) {
    uint32_t a;
    asm("{ .reg .u64 t; cvta.to.shared.u64 t, %1; cvt.u32.u64 %0, t; }" : "=r"(a) : "l"(p));
    return a;
}
__device__ __forceinline__ void cpasync16(uint32_t d, const void* g) {
    asm volatile("cp.async.cg.shared.global [%0], [%1], 16;" :: "r"(d), "l"(g));
}
#define CP_COMMIT() asm volatile("cp.async.commit_group;" ::: "memory")
#define CP_WAIT0()  asm volatile("cp.async.wait_group 0;" ::: "memory")

// image byte offset within a row for element k (k-pair permute + region rotation by row)
__device__ __forceinline__ int img_off(int k, int row) {
    int bblk = k >> 6;             // 64-k block (128 B)
    int c    = (k >> 4) & 3;       // 16-k chunk (32 B region)
    int kk   = k & 15;
    int p    = kk >> 1;            // pair index 0..7
    int slot = ((p & 3) << 1) | (p >> 2);   // pairs ordered (0,4,1,5,2,6,3,7)
    int reg  = (c + row) & 3;      // rotate 32B regions by row -> bank-conflict-free frags
    return bblk * 128 + reg * 32 + slot * 4 + (kk & 1) * 2;
}

// ---------------- LN stats + bf16 swizzled image of X ----------------
__global__ void ln_stats_kernel(const float* __restrict__ X) {
    __shared__ __align__(16) uint16_t img[8][512];
    int warp = threadIdx.x >> 5, lane = threadIdx.x & 31;
    int row  = blockIdx.x * 8 + warp;
    const float* xr = X + (size_t)row * INPv;
    float4 v[4];
    float s = 0.f, s2 = 0.f;
#pragma unroll
    for (int j = 0; j < 4; j++) {
        v[j] = *(const float4*)(xr + lane * 4 + 128 * j);
        s  += v[j].x + v[j].y + v[j].z + v[j].w;
        s2 += v[j].x * v[j].x + v[j].y * v[j].y + v[j].z * v[j].z + v[j].w * v[j].w;
    }
#pragma unroll
    for (int off = 16; off; off >>= 1) {
        s  += __shfl_down_sync(0xffffffffu, s,  off);
        s2 += __shfl_down_sync(0xffffffffu, s2, off);
    }
    if (!lane) {
        float m   = s * (1.f / INPv);
        float var = s2 * (1.f / INPv) - m * m;
        g_stats[row * 2]     = m;
        g_stats[row * 2 + 1] = rsqrtf(var + 1e-5f);
    }
    // bf16 image (pair-permuted, region-rotated)
#pragma unroll
    for (int j = 0; j < 4; j++) {
        int k0 = lane * 4 + 128 * j;
        float vals[4] = {v[j].x, v[j].y, v[j].z, v[j].w};
#pragma unroll
        for (int t = 0; t < 2; t++) {
            int k = k0 + 2 * t;
            __nv_bfloat162 h2 = __floats2bfloat162_rn(vals[2 * t], vals[2 * t + 1]);
            *(uint32_t*)((char*)img[warp] + img_off(k, row)) = *(uint32_t*)&h2;
        }
    }
    __syncwarp();
    uint4* srcp = (uint4*)img[warp];
    uint4* dstp = (uint4*)(g_xh + (size_t)row * 512);
    dstp[lane]      = srcp[lane];
    dstp[lane + 32] = srcp[lane + 32];
}

// ---------------- column sums of Wk|Wv (parallel) ----------------
__global__ void wsum_kernel(const float* __restrict__ Wk, const float* __restrict__ Wv) {
    __shared__ float red[4][64];
    int b = blockIdx.x;                 // 8 blocks x 64 cols
    int c0 = b * 64;
    int col = threadIdx.x & 63, part = threadIdx.x >> 6;
    const float* W = (c0 < 256) ? Wk : Wv;
    int cc = (c0 & 255) + col;
    float s = 0.f;
    for (int k = part * 128; k < part * 128 + 128; k++) s += W[k * 256 + cc];
    red[part][col] = s;
    __syncthreads();
    if (threadIdx.x < 64) {
        g_wsum[c0 + threadIdx.x] = red[0][threadIdx.x] + red[1][threadIdx.x]
                                 + red[2][threadIdx.x] + red[3][threadIdx.x];
    }
}

// ---------------- transposed fused-W bf16 image: g_wth[n][k-image] ----------------
__global__ void transpose_w_kernel(const float* __restrict__ Wk, const float* __restrict__ Wv) {
    __shared__ float t[32][33];
    int n0 = blockIdx.x * 32, k0 = blockIdx.y * 32;
    int tx = threadIdx.x, ty = threadIdx.y;     // (32, 8)
    const float* W = (n0 < 256) ? Wk : Wv;
    int col0 = n0 & 255;
#pragma unroll
    for (int j = 0; j < 4; j++) {
        int k = k0 + ty + 8 * j;
        t[ty + 8 * j][tx] = W[(size_t)k * 256 + col0 + tx];
    }
    __syncthreads();
#pragma unroll
    for (int j = 0; j < 4; j++) {
        int n = n0 + ty + 8 * j;
        int k = k0 + tx;
        __nv_bfloat16 h = __float2bfloat16(t[tx][ty + 8 * j]);
        g_wth[(size_t)n * 512 + (img_off(k, n) >> 1)] = *(uint16_t*)&h;
    }
}

// ---------------- bf16 mma.sync projection: k|v = LN(x) @ [Wk|Wv] ----------------
// CTA 128(M)x128(N), K staged 64 at a time (8 stages), double-buffered cp.async.
#define STG 16384   // 128 rows x 128 B per stage tile

__global__ __launch_bounds__(256, 2)
void proj_mma_kernel() {
    extern __shared__ char dsm[];
    uint32_t sb = smem_u32(dsm);
    int n0   = blockIdx.x * 128;
    int row0 = blockIdx.y * 128;
    int tid  = threadIdx.x;
    int wid  = tid >> 5, lane = tid & 31;
    int warp_m = wid >> 2, warp_n = wid & 3;
    int mb = warp_m * 64, nb = warp_n * 32;
    int grp = lane >> 2, q = lane & 3;
    int lr = tid >> 1, lh = tid & 1;

    float acc[4][4][4];
#pragma unroll
    for (int f = 0; f < 4; f++)
#pragma unroll
        for (int g = 0; g < 4; g++)
#pragma unroll
            for (int c = 0; c < 4; c++) acc[f][g][c] = 0.f;

    auto issue = [&](int s, int buf) {
        const char* srcA = (const char*)g_xh  + (size_t)(row0 + lr) * 1024 + s * 128 + lh * 64;
        const char* srcB = (const char*)g_wth + (size_t)(n0   + lr) * 1024 + s * 128 + lh * 64;
        uint32_t dA = sb + buf * STG       + lr * 128 + lh * 64;
        uint32_t dB = sb + (2 + buf) * STG + lr * 128 + lh * 64;
#pragma unroll
        for (int gi = 0; gi < 4; gi++) {
            cpasync16(dA + gi * 16, srcA + gi * 16);
            cpasync16(dB + gi * 16, srcB + gi * 16);
        }
    };

    issue(0, 0);
    CP_COMMIT();

    int buf = 0;
    for (int s = 0; s < 8; s++) {
        CP_WAIT0();
        __syncthreads();
        if (s < 7) { issue(s + 1, buf ^ 1); CP_COMMIT(); }

        const char* As = dsm + buf * STG;
        const char* Bs = dsm + (2 + buf) * STG;
#pragma unroll
        for (int c = 0; c < 4; c++) {
            uint2 bfr[4];
#pragma unroll
            for (int g = 0; g < 4; g++) {
                int rn = nb + g * 8 + grp;
                bfr[g] = *(const uint2*)(Bs + rn * 128 + ((c + rn) & 3) * 32 + q * 8);
            }
#pragma unroll
            for (int f = 0; f < 4; f++) {
                int r0 = mb + f * 16 + grp;
                int r1 = r0 + 8;
                uint2 aa = *(const uint2*)(As + r0 * 128 + ((c + r0) & 3) * 32 + q * 8);
                uint2 ab = *(const uint2*)(As + r1 * 128 + ((c + r1) & 3) * 32 + q * 8);
#pragma unroll
                for (int g = 0; g < 4; g++) {
                    asm volatile(
                        "mma.sync.aligned.m16n8k16.row.col.f32.bf16.bf16.f32 "
                        "{%0,%1,%2,%3}, {%4,%5,%6,%7}, {%8,%9}, {%0,%1,%2,%3};"
                        : "+f"(acc[f][g][0]), "+f"(acc[f][g][1]),
                          "+f"(acc[f][g][2]), "+f"(acc[f][g][3])
                        : "r"(aa.x), "r"(ab.x), "r"(aa.y), "r"(ab.y),
                          "r"(bfr[g].x), "r"(bfr[g].y));
                }
            }
        }
        buf ^= 1;
    }

    // epilogue: LN fold + store bf16 pairs
    __nv_bfloat16* kh = (__nv_bfloat16*)g_k;
    __nv_bfloat16* vh = (__nv_bfloat16*)g_v;
#pragma unroll
    for (int f = 0; f < 4; f++) {
        int r0g = row0 + mb + f * 16 + grp;
        int r1g = r0g + 8;
        float m0 = g_stats[r0g * 2],     s0 = g_stats[r0g * 2 + 1];
        float m1 = g_stats[r1g * 2],     s1 = g_stats[r1g * 2 + 1];
        float mr0 = m0 * s0, mr1 = m1 * s1;
#pragma unroll
        for (int g = 0; g < 4; g++) {
            int nglob = n0 + nb + g * 8 + q * 2;
            float ws0 = g_wsum[nglob], ws1 = g_wsum[nglob + 1];
            __nv_bfloat162 o0 = __floats2bfloat162_rn(
                s0 * acc[f][g][0] - mr0 * ws0, s0 * acc[f][g][1] - mr0 * ws1);
            __nv_bfloat162 o1 = __floats2bfloat162_rn(
                s1 * acc[f][g][2] - mr1 * ws0, s1 * acc[f][g][3] - mr1 * ws1);
            if (nglob < 256) {
                *(__nv_bfloat162*)(kh + (size_t)r0g * 256 + nglob) = o0;
                *(__nv_bfloat162*)(kh + (size_t)r1g * 256 + nglob) = o1;
            } else {
                *(__nv_bfloat162*)(vh + (size_t)r0g * 256 + nglob - 256) = o0;
                *(__nv_bfloat162*)(vh + (size_t)r1g * 256 + nglob - 256) = o1;
            }
        }
    }
}

// ---------------- slots init ----------------
__global__ void init_slots_kernel(const float* __restrict__ noise,
                                  const float* __restrict__ mu,
                                  const float* __restrict__ ls) {
    int i = blockIdx.x * 256 + threadIdx.x;   // 65536
    int d = i & 255;
    g_slots[i] = mu[d] + expf(ls[d]) * noise[i];
}

// ---------------- block LayerNorm over 256 (blockDim=256) ----------------
__device__ __forceinline__ float block_ln256(float v) {
    __shared__ float red[66];
    float s = v, s2 = v * v;
    int lane = threadIdx.x & 31, warp = threadIdx.x >> 5;
#pragma unroll
    for (int off = 16; off; off >>= 1) {
        s  += __shfl_down_sync(0xffffffffu, s,  off);
        s2 += __shfl_down_sync(0xffffffffu, s2, off);
    }
    if (!lane) { red[warp] = s; red[32 + warp] = s2; }
    __syncthreads();
    if (threadIdx.x == 0) {
        float ts = 0.f, t2 = 0.f;
#pragma unroll
        for (int i = 0; i < 8; i++) { ts += red[i]; t2 += red[32 + i]; }
        float m   = ts * (1.f / 256.f);
        float var = t2 * (1.f / 256.f) - m * m;
        red[64] = m;
        red[65] = rsqrtf(var + 1e-5f);
    }
    __syncthreads();
    return (v - red[64]) * red[65];
}

// ---------------- slots LN + q = s_ln @ Wq + zero accumulators ----------------
__global__ void slot_ln_q_kernel(const float* __restrict__ Wq) {
    __shared__ float sln[256];
    int row = blockIdx.x, t = threadIdx.x;
    float v  = g_slots[row * 256 + t];
    float nv = block_ln256(v);
    g_sln[row * 256 + t] = nv;
    sln[t] = nv;
    g_upd[row * 256 + t] = 0.f;
    if (t == 0) g_colsum[row] = 0.f;
    __syncthreads();
    float a0 = 0.f, a1 = 0.f, a2 = 0.f, a3 = 0.f;
#pragma unroll 2
    for (int k = 0; k < 256; k += 4) {
        a0 += sln[k]     * Wq[(k)     * 256 + t];
        a1 += sln[k + 1] * Wq[(k + 1) * 256 + t];
        a2 += sln[k + 2] * Wq[(k + 2) * 256 + t];
        a3 += sln[k + 3] * Wq[(k + 3) * 256 + t];
    }
    g_q[row * 256 + t] = (a0 + a1) + (a2 + a3);
}

// ---------------- fused attention + updates (bf16 k/v, round-9 dataflow) ----------------
// phase1: warp handles 16 n-rows in 4 groups of 4; 4 k-rows live in registers,
//         each q LDS.64 feeds 4 rows (x2 FMA); 5-level shuffle reduce; softmax on lane 0.
// phase2: thread t owns d=t; p^T v with bf16 v.
__global__ __launch_bounds__(256)
void attn_upd_kernel() {
    __shared__ __align__(16) float qs[2048];       // [8][256]
    __shared__ float ps[128 * 8];
    int b  = blockIdx.y;
    int n0 = blockIdx.x * 128;
    int tid = threadIdx.x;
    int warp = tid >> 5, lane = tid & 31;
    const __nv_bfloat16* kh = (const __nv_bfloat16*)g_k;
    const __nv_bfloat16* vh = (const __nv_bfloat16*)g_v;

    for (int i = tid; i < 2048; i += 256) qs[i] = g_q[(size_t)b * 2048 + i];
    __syncthreads();

    const float scale = 0.0625f;   // 1/sqrt(256)
    float csum[8] = {};
#pragma unroll
    for (int g = 0; g < 4; g++) {
        int nb = warp * 16 + g * 4;
        const uint32_t* kp = (const uint32_t*)(kh + ((size_t)(b * Nv + n0 + nb)) * 256);
        float part[4][8] = {};
#pragma unroll
        for (int j = 0; j < 4; j++) {
            int pi = lane + 32 * j;            // bf16-pair index 0..127
            float2 kv[4];
#pragma unroll
            for (int i = 0; i < 4; i++)
                kv[i] = __bfloat1622float2(*(const __nv_bfloat162*)&kp[i * 128 + pi]);
#pragma unroll
            for (int s = 0; s < 8; s++) {
                float2 qv = *(const float2*)(qs + s * 256 + 2 * pi);
#pragma unroll
                for (int i = 0; i < 4; i++)
                    part[i][s] += kv[i].x * qv.x + kv[i].y * qv.y;
            }
        }
#pragma unroll
        for (int i = 0; i < 4; i++)
#pragma unroll
            for (int s = 0; s < 8; s++)
#pragma unroll
                for (int off = 16; off; off >>= 1)
                    part[i][s] += __shfl_down_sync(0xffffffffu, part[i][s], off);
        if (lane == 0) {
#pragma unroll
            for (int i = 0; i < 4; i++) {
                float m = -1e30f;
#pragma unroll
                for (int s = 0; s < 8; s++) m = fmaxf(m, part[i][s] * scale);
                float e[8], sum = 0.f;
#pragma unroll
                for (int s = 0; s < 8; s++) { e[s] = __expf(part[i][s] * scale - m); sum += e[s]; }
                float inv = 1.f / sum;
                int nl = warp * 16 + g * 4 + i;
#pragma unroll
                for (int s = 0; s < 8; s++) {
                    float p = e[s] * inv + 1e-8f;
                    ps[nl * 8 + s] = p;
                    csum[s] += p;
                }
            }
        }
    }
    if (lane == 0) {
#pragma unroll
        for (int s = 0; s < 8; s++) atomicAdd(&g_colsum[b * 8 + s], csum[s]);
    }
    __syncthreads();

    // phase 2: p^T v
    int d = tid;
    float acc[8] = {};
    const __nv_bfloat16* vb = vh + ((size_t)(b * Nv + n0)) * 256;
#pragma unroll 4
    for (int n = 0; n < 128; n++) {
        float vv = __bfloat162float(vb[(size_t)n * 256 + d]);
#pragma unroll
        for (int s = 0; s < 8; s++) acc[s] += ps[n * 8 + s] * vv;
    }
#pragma unroll
    for (int s = 0; s < 8; s++) atomicAdd(&g_upd[(b * 8 + s) * 256 + d], acc[s]);
}

// ---------------- merged GRU gate GEMMs (gx and gh in one launch) ----------------
__global__ __launch_bounds__(256)
void gru_gemm_kernel(const float* __restrict__ wih, const float* __restrict__ whh,
                     const float* __restrict__ bih, const float* __restrict__ bhh) {
    __shared__ float As[8 * 68];
    __shared__ float Bs[8 * 68];
    int path = blockIdx.x / 12;
    int bxl  = blockIdx.x - path * 12;
    const float* A    = path ? g_sln : g_upd;
    const float* Bm   = path ? whh   : wih;
    const float* bias = path ? bhh   : bih;
    float* C          = path ? g_gh  : g_gx;
    const int N = 768, K = 256;
    int bm = blockIdx.y * 64, bn = bxl * 64;
    int tid = threadIdx.x;
    int ty = tid >> 4, tx = tid & 15;

    float inv = 1.f;
    int arow = bm + (tid >> 1);
    if (tid < 128 && path == 0) inv = 1.f / g_colsum[arow];

    float acc[4][4] = {};
    for (int k0 = 0; k0 < K; k0 += 8) {
        if (tid < 128) {
            int row = tid >> 1, part = tid & 1;
            float4 av = *(const float4*)(A + (size_t)(bm + row) * K + k0 + part * 4);
            int kk = part * 4;
            As[(kk + 0) * 68 + row] = av.x * inv;
            As[(kk + 1) * 68 + row] = av.y * inv;
            As[(kk + 2) * 68 + row] = av.z * inv;
            As[(kk + 3) * 68 + row] = av.w * inv;
        } else {
            int t2 = tid - 128;
            int n = t2 >> 1, part = t2 & 1;
            float4 bv = *(const float4*)(Bm + (size_t)(bn + n) * K + k0 + part * 4);
            int kk = part * 4;
            Bs[(kk + 0) * 68 + n] = bv.x;
            Bs[(kk + 1) * 68 + n] = bv.y;
            Bs[(kk + 2) * 68 + n] = bv.z;
            Bs[(kk + 3) * 68 + n] = bv.w;
        }
        __syncthreads();
#pragma unroll
        for (int kk = 0; kk < 8; kk++) {
            float4 a = *(const float4*)(As + kk * 68 + ty * 4);
            float4 bq = *(const float4*)(Bs + kk * 68 + tx * 4);
            float av[4] = {a.x, a.y, a.z, a.w};
            float bw[4] = {bq.x, bq.y, bq.z, bq.w};
#pragma unroll
            for (int i = 0; i < 4; i++)
#pragma unroll
                for (int j = 0; j < 4; j++)
                    acc[i][j] += av[i] * bw[j];
        }
        __syncthreads();
    }
#pragma unroll
    for (int i = 0; i < 4; i++) {
        int r = bm + ty * 4 + i;
#pragma unroll
        for (int j = 0; j < 4; j++) {
            int c = bn + tx * 4 + j;
            C[(size_t)r * N + c] = acc[i][j] + bias[c];
        }
    }
}

// ---------------- small GEMM: C[M,N] = A[M,K] @ B + bias (B k-major) ----------------
template<bool RELU, bool ACCUM>
__global__ __launch_bounds__(256)
void gemm64_kernel(const float* __restrict__ A, const float* __restrict__ Bm,
                   const float* __restrict__ bias, float* __restrict__ C,
                   int M, int N, int K, float* __restrict__ out2) {
    __shared__ float As[8 * 68];
    __shared__ float Bs[8 * 68];
    int bm = blockIdx.y * 64, bn = blockIdx.x * 64;
    int tid = threadIdx.x;
    int ty = tid >> 4, tx = tid & 15;
    float acc[4][4] = {};
    for (int k0 = 0; k0 < K; k0 += 8) {
        if (tid < 128) {
            int row = tid >> 1, part = tid & 1;
            float4 av = *(const float4*)(A + (size_t)(bm + row) * K + k0 + part * 4);
            int kk = part * 4;
            As[(kk + 0) * 68 + row] = av.x;
            As[(kk + 1) * 68 + row] = av.y;
            As[(kk + 2) * 68 + row] = av.z;
            As[(kk + 3) * 68 + row] = av.w;
        } else {
            int t2 = tid - 128;
            int kk = t2 >> 4, q = t2 & 15;
            float4 bv = *(const float4*)(Bm + (size_t)(k0 + kk) * N + bn + q * 4);
            *(float4*)(Bs + kk * 68 + q * 4) = bv;
        }
        __syncthreads();
#pragma unroll
        for (int kk = 0; kk < 8; kk++) {
            float4 a = *(const float4*)(As + kk * 68 + ty * 4);
            float4 bq = *(const float4*)(Bs + kk * 68 + tx * 4);
            float av[4] = {a.x, a.y, a.z, a.w};
            float bw[4] = {bq.x, bq.y, bq.z, bq.w};
#pragma unroll
            for (int i = 0; i < 4; i++)
#pragma unroll
                for (int j = 0; j < 4; j++)
                    acc[i][j] += av[i] * bw[j];
        }
        __syncthreads();
    }
#pragma unroll
    for (int i = 0; i < 4; i++) {
        int r = bm + ty * 4 + i;
#pragma unroll
        for (int j = 0; j < 4; j++) {
            int c = bn + tx * 4 + j;
            float v = acc[i][j] + bias[c];
            if (RELU) v = fmaxf(v, 0.f);
            if (ACCUM) {
                float nv = C[(size_t)r * N + c] + v;
                C[(size_t)r * N + c] = nv;
                if (out2) out2[(size_t)r * N + c] = nv;
            } else {
                C[(size_t)r * N + c] = v;
            }
        }
    }
}

// ---------------- GRU combine + LN(y) fused ----------------
__global__ void gru_lny_kernel() {
    int row = blockIdx.x, t = threadIdx.x;
    int i = row * 256 + t;
    const float* gx = g_gx + row * 768;
    const float* gh = g_gh + row * 768;
    float r  = 1.f / (1.f + __expf(-(gx[t] + gh[t])));
    float z  = 1.f / (1.f + __expf(-(gx[256 + t] + gh[256 + t])));
    float nn = tanhf(gx[512 + t] + r * gh[512 + t]);
    float h  = (1.f - z) * nn + z * g_sln[i];
    g_slots[i] = h;
    g_y[i] = block_ln256(h);
}

// =====================================================================
extern "C" void kernel_launch(void* const* d_in, const int* in_sizes, int n_in,
                              void* d_out, int out_size) {
    (void)in_sizes; (void)n_in; (void)out_size;
    const float* inputs = (const float*)d_in[0];
    const float* noise  = (const float*)d_in[1];
    const float* Wk     = (const float*)d_in[2];
    const float* Wv     = (const float*)d_in[3];
    const float* Wq     = (const float*)d_in[4];
    const float* mu     = (const float*)d_in[5];
    const float* ls     = (const float*)d_in[6];
    const float* wih    = (const float*)d_in[7];
    const float* whh    = (const float*)d_in[8];
    const float* bih    = (const float*)d_in[9];
    const float* bhh    = (const float*)d_in[10];
    const float* w1     = (const float*)d_in[11];
    const float* b1     = (const float*)d_in[12];
    const float* w2     = (const float*)d_in[13];
    const float* b2     = (const float*)d_in[14];

    float *p_h1, *p_y, *p_slots;
    cudaGetSymbolAddress((void**)&p_h1,    g_h1);
    cudaGetSymbolAddress((void**)&p_y,     g_y);
    cudaGetSymbolAddress((void**)&p_slots, g_slots);

    cudaFuncSetAttribute(proj_mma_kernel,
                         cudaFuncAttributeMaxDynamicSharedMemorySize, 4 * STG);

    ln_stats_kernel<<<ROWSv / 8, 256>>>(inputs);
    wsum_kernel<<<8, 256>>>(Wk, Wv);
    transpose_w_kernel<<<dim3(16, 16), dim3(32, 8)>>>(Wk, Wv);
    proj_mma_kernel<<<dim3(4, 1024), 256, 4 * STG>>>();
    init_slots_kernel<<<256, 256>>>(noise, mu, ls);

    for (int it = 0; it < 3; it++) {
        slot_ln_q_kernel<<<256, 256>>>(Wq);
        attn_upd_kernel<<<dim3(32, 32), 256>>>();
        gru_gemm_kernel<<<dim3(24, 4), 256>>>(wih, whh, bih, bhh);
        gru_lny_kernel<<<256, 256>>>();
        gemm64_kernel<true,  false><<<dim3(8, 4), 256>>>(p_y,  w1, b1, p_h1,    256, 512, 256, nullptr);
        gemm64_kernel<false, true ><<<dim3(4, 4), 256>>>(p_h1, w2, b2, p_slots, 256, 256, 512,
                                                         (it == 2) ? (float*)d_out : nullptr);
    }
}